// round 6
// baseline (speedup 1.0000x reference)
#include <cuda_runtime.h>
#include <cuda_bf16.h>
#include <cstdint>
#include <cstddef>

#define NP 1024
#define NL 32768
#define NU 64
#define NS 32            /* segments */
#define SEG 1024         /* NL/NS */
#define NT 8             /* row tiles */
#define MT 128           /* rows per main block */
#define KC 64            /* K per chunk */
#define NCH (SEG/KC)     /* 16 */

__device__ float g_partial[(size_t)NS * NP * NU];
__device__ float2 g_agg[(size_t)NS * NP];
__device__ int g_flag[NT * NS];                    // phase-1 publish flags
__device__ int g_bflag[NS];                        // B-slice-ready flags
__device__ __nv_bfloat16 g_bhi[(size_t)NU * NL];   // kernel^T hi, [n][k]
__device__ __nv_bfloat16 g_blo[(size_t)NU * NL];   // kernel^T lo

__device__ __forceinline__ float finf()  { return __int_as_float(0x7f800000); }
__device__ __forceinline__ float fninf() { return __int_as_float(0xff800000); }
__device__ __forceinline__ float fclamp(float v, float a, float b) {
    return fminf(fmaxf(v, a), b);
}
__device__ __forceinline__ uint32_t bfpack(float e0, float e1) {
    uint32_t r;
    asm("cvt.rn.bf16x2.f32 %0, %1, %2;" : "=r"(r) : "f"(e1), "f"(e0));
    return r;
}
__device__ __forceinline__ uint32_t s2u(const void* p) {
    uint32_t a;
    asm("{ .reg .u64 t; cvta.to.shared.u64 t, %1; cvt.u32.u64 %0, t; }"
        : "=r"(a) : "l"(p));
    return a;
}
__device__ __forceinline__ void ldsm4(uint32_t* r, uint32_t a) {
    asm volatile("ldmatrix.sync.aligned.m8n8.x4.shared.b16 {%0,%1,%2,%3}, [%4];"
        : "=r"(r[0]), "=r"(r[1]), "=r"(r[2]), "=r"(r[3]) : "r"(a));
}
__device__ __forceinline__ void mma_bf16(float* d, const uint32_t* a,
                                         uint32_t b0, uint32_t b1) {
    asm volatile(
        "mma.sync.aligned.m16n8k16.row.col.f32.bf16.bf16.f32 "
        "{%0,%1,%2,%3}, {%4,%5,%6,%7}, {%8,%9}, {%0,%1,%2,%3};"
        : "+f"(d[0]), "+f"(d[1]), "+f"(d[2]), "+f"(d[3])
        : "r"(a[0]), "r"(a[1]), "r"(a[2]), "r"(a[3]), "r"(b0), "r"(b1));
}

#define XS2_STR 132                        /* phase-1 staging stride (floats) */
#define XS_STR 68                          /* phase-2 staging stride (floats) */
#define YH_OFF 34816
#define Y_STRB 144
#define YL_OFF (YH_OFF + 128 * Y_STRB)     /* 53248 */
#define BH_OFF (YL_OFF + 128 * Y_STRB)     /* 71680 */
#define BL_OFF (BH_OFF + 64 * Y_STRB)      /* 80896 */
#define SM_TOT (BL_OFF + 64 * Y_STRB)      /* 90112 */

__global__ __launch_bounds__(256, 2) void k_main(const float* __restrict__ x,
                                                 const float* __restrict__ pw,
                                                 const float* __restrict__ kern) {
    extern __shared__ char smem[];
    float* xs = (float*)smem;
    uint32_t sb = s2u(smem);

    int tile = blockIdx.x;        // 0..7
    int s    = blockIdx.y;        // 0..31
    int t    = threadIdx.x;
    int w    = t >> 5, lane = t & 31;
    int r0   = tile * MT;
    const size_t xoff = (size_t)s * SEG;

    // ---------- B-prep: tile-0 blocks build the bf16 hi/lo B slice ----------
    if (tile == 0) {
        for (int u = 0; u < 16; ++u) {
            int k0 = s * SEG + u * KC;
            __syncthreads();
            #pragma unroll
            for (int q = 0; q < 4; ++q) {
                int g = q * 256 + t;
                int kr = g >> 4, nc = (g & 15) * 4;
                *(float4*)(xs + kr * XS_STR + nc) =
                    *(const float4*)(kern + (size_t)(k0 + kr) * NU + nc);
            }
            __syncthreads();
            int n = t & 63, g2 = t >> 6;
            uint32_t h[8], l[8];
            #pragma unroll
            for (int i = 0; i < 8; ++i) {
                float a = xs[(g2 * 16 + 2 * i) * XS_STR + n];
                float b = xs[(g2 * 16 + 2 * i + 1) * XS_STR + n];
                uint32_t hp = bfpack(a, b);
                float ha = __uint_as_float(hp << 16);
                float hb = __uint_as_float(hp & 0xffff0000u);
                h[i] = hp;
                l[i] = bfpack(a - ha, b - hb);
            }
            size_t base = (size_t)n * NL + k0 + g2 * 16;
            *(uint4*)&g_bhi[base]     = make_uint4(h[0], h[1], h[2], h[3]);
            *(uint4*)&g_bhi[base + 8] = make_uint4(h[4], h[5], h[6], h[7]);
            *(uint4*)&g_blo[base]     = make_uint4(l[0], l[1], l[2], l[3]);
            *(uint4*)&g_blo[base + 8] = make_uint4(l[4], l[5], l[6], l[7]);
        }
        __threadfence();
        __syncthreads();
        if (t == 0) atomicExch(&g_bflag[s], 1);
    }

    // ---------- phase 1: per-row aggregate, split across two half-threads ----
    int r = t & 127, half = t >> 7;
    int row = r0 + r;
    float pwv = pw[row];
    float A = fninf(), B = finf();

    for (int i = 0; i < 8; ++i) {
        __syncthreads();
        #pragma unroll
        for (int q = 0; q < 16; ++q) {
            int g = q * 256 + t;
            int rr = g >> 5, cc = g & 31;
            size_t gcol = (cc < 16) ? ((size_t)i * 64 + cc * 4)
                                    : (512 + (size_t)i * 64 + (cc - 16) * 4);
            int scol = (cc < 16) ? cc * 4 : 64 + (cc - 16) * 4;
            float4 v = *(const float4*)(x + (size_t)(r0 + rr) * NL + xoff + gcol);
            *(float4*)(xs + rr * XS2_STR + scol) = v;
        }
        __syncthreads();

        const float4* xv = (const float4*)(xs + r * XS2_STR + half * 64);
        int jbase = s * SEG + half * 512 + i * 64;
        int qs = 0;
        if (jbase == 0) {
            float4 v = xv[0];
            A = v.x; B = v.x;            // j==0: clamp (p0,p0)
            float vv[3] = {v.y, v.z, v.w};
            #pragma unroll
            for (int e = 0; e < 3; ++e) {
                float a = vv[e] * pwv, b = a + 1.0f;
                A = fclamp(A, a, b);
                B = fclamp(B, a, b);
            }
            qs = 1;
        }
        for (int q = qs; q < 16; ++q) {
            float4 v = xv[q];
            float vv[4] = {v.x, v.y, v.z, v.w};
            #pragma unroll
            for (int e = 0; e < 4; ++e) {
                float a = vv[e] * pwv, b = a + 1.0f;
                A = fclamp(A, a, b);
                B = fclamp(B, a, b);
            }
        }
    }
    // compose the two halves and publish
    {
        float2* ex = (float2*)(smem + BH_OFF);
        if (half) ex[r] = make_float2(A, B);
        __syncthreads();
        if (!half) {
            float2 ab = ex[r];
            g_agg[(size_t)s * NP + row] =
                make_float2(fclamp(A, ab.x, ab.y), fclamp(B, ab.x, ab.y));
        }
        __threadfence();
        __syncthreads();
        if (t == 0) atomicExch(&g_flag[tile * NS + s], 1);
    }

    // ---------- lookback ----------
    float y = 0.0f;
    if (s > 0) {
        if (t < s)
            while (atomicAdd(&g_flag[tile * NS + t], 0) == 0) { }
        __syncthreads();
        if (t < 128) {
            for (int s2 = 0; s2 < s; ++s2) {
                float2 ab = __ldcg(&g_agg[(size_t)s2 * NP + row]);
                y = fclamp(y, ab.x, ab.y);
            }
        }
    }
    // wait for B slice
    if (t == 0) {
        while (atomicAdd(&g_bflag[s], 0) == 0) { }
        __threadfence();
    }
    __syncthreads();

    // ---------- phase 2: scan + bf16-split mma ----------
    float acc[8][4];
    #pragma unroll
    for (int j = 0; j < 8; ++j)
        #pragma unroll
        for (int q = 0; q < 4; ++q) acc[j][q] = 0.0f;

    for (int c = 0; c < NCH; ++c) {
        __syncthreads();
        #pragma unroll
        for (int q = 0; q < 8; ++q) {
            int g = q * 256 + t;
            int rr = g >> 4, cc = g & 15;
            float4 v = *(const float4*)(x + (size_t)(r0 + rr) * NL
                                          + xoff + c * KC + cc * 4);
            *(float4*)(xs + rr * XS_STR + cc * 4) = v;
        }
        __syncthreads();

        if (t < 128) {
            // warps 0-3: sequential scan of own row; emit bf16 hi/lo
            const float4* xv = (const float4*)(xs + t * XS_STR);
            int j0 = s * SEG + c * KC;
            #pragma unroll
            for (int q = 0; q < 8; ++q) {
                float4 v0 = xv[2 * q], v1 = xv[2 * q + 1];
                float vv[8] = {v0.x, v0.y, v0.z, v0.w, v1.x, v1.y, v1.z, v1.w};
                float ya[8];
                int es = 0;
                if (j0 == 0 && q == 0) { y = vv[0]; ya[0] = y; es = 1; }
                #pragma unroll
                for (int e = 0; e < 8; ++e) {
                    if (e < es) continue;
                    float a = vv[e] * pwv, b = a + 1.0f;
                    y = fclamp(y, a, b);
                    ya[e] = y;
                }
                uint32_t h[4], l[4];
                #pragma unroll
                for (int pp = 0; pp < 4; ++pp) {
                    float e0 = ya[2 * pp], e1 = ya[2 * pp + 1];
                    uint32_t hp = bfpack(e0, e1);
                    float h0 = __uint_as_float(hp << 16);
                    float h1 = __uint_as_float(hp & 0xffff0000u);
                    h[pp] = hp;
                    l[pp] = bfpack(e0 - h0, e1 - h1);
                }
                *(uint4*)(smem + YH_OFF + t * Y_STRB + q * 16) =
                    make_uint4(h[0], h[1], h[2], h[3]);
                *(uint4*)(smem + YL_OFF + t * Y_STRB + q * 16) =
                    make_uint4(l[0], l[1], l[2], l[3]);
            }
        } else {
            // warps 4-7: stage B hi/lo tiles for this chunk
            int t2 = t - 128;
            int n = t2 >> 1, colb = (t2 & 1) * 4;
            const uint4* hs = (const uint4*)(g_bhi + (size_t)n * NL + xoff + c * KC) + colb;
            const uint4* ls = (const uint4*)(g_blo + (size_t)n * NL + xoff + c * KC) + colb;
            #pragma unroll
            for (int q = 0; q < 4; ++q) {
                *(uint4*)(smem + BH_OFF + n * Y_STRB + (colb + q) * 16) = hs[q];
                *(uint4*)(smem + BL_OFF + n * Y_STRB + (colb + q) * 16) = ls[q];
            }
        }
        __syncthreads();

        // all 8 warps: ldmatrix + mma; warp w owns rows [w*16, w*16+16)
        #pragma unroll
        for (int kk = 0; kk < 4; ++kk) {
            uint32_t ah[4], al[4];
            uint32_t ra = sb + YH_OFF
                + (uint32_t)(w * 16 + (lane & 15)) * Y_STRB
                + (uint32_t)(kk * 16 + (lane >> 4) * 8) * 2;
            ldsm4(ah, ra);
            ldsm4(al, ra + (YL_OFF - YH_OFF));
            #pragma unroll
            for (int np = 0; np < 4; ++np) {
                uint32_t rb = sb + BH_OFF
                    + (uint32_t)(np * 16 + (lane & 7) + ((lane >> 4) & 1) * 8) * Y_STRB
                    + (uint32_t)(kk * 16 + ((lane >> 3) & 1) * 8) * 2;
                uint32_t bh[4], bl[4];
                ldsm4(bh, rb);
                ldsm4(bl, rb + (BL_OFF - BH_OFF));
                mma_bf16(acc[2 * np],     ah, bh[0], bh[1]);
                mma_bf16(acc[2 * np],     ah, bl[0], bl[1]);
                mma_bf16(acc[2 * np],     al, bh[0], bh[1]);
                mma_bf16(acc[2 * np + 1], ah, bh[2], bh[3]);
                mma_bf16(acc[2 * np + 1], ah, bl[2], bl[3]);
                mma_bf16(acc[2 * np + 1], al, bh[2], bh[3]);
            }
        }
    }

    // ---------- epilogue ----------
    #pragma unroll
    for (int nt = 0; nt < 8; ++nt) {
        int p = r0 + w * 16 + (lane >> 2);
        int u = nt * 8 + (lane & 3) * 2;
        *(float2*)&g_partial[((size_t)s * NP + p) * NU + u] =
            make_float2(acc[nt][0], acc[nt][1]);
        *(float2*)&g_partial[((size_t)s * NP + p + 8) * NU + u] =
            make_float2(acc[nt][2], acc[nt][3]);
    }
}

// ---------------------------------------------------------------------------
// Reduction + bias + tanh; resets flags for the next graph replay.
// ---------------------------------------------------------------------------
__global__ __launch_bounds__(256) void k_reduce(const float* __restrict__ bias,
                                                float* __restrict__ out) {
    int gid = blockIdx.x * 256 + threadIdx.x;       // float4 units
    if (blockIdx.x == 0) {
        g_flag[threadIdx.x] = 0;
        if (threadIdx.x < NS) g_bflag[threadIdx.x] = 0;
    }
    float4 sum = *(const float4*)(bias + ((gid * 4) & (NU - 1)));
    #pragma unroll 8
    for (int s2 = 0; s2 < NS; ++s2) {
        float4 v = *(const float4*)(g_partial + (size_t)s2 * (NP * NU) + (size_t)gid * 4);
        sum.x += v.x; sum.y += v.y; sum.z += v.z; sum.w += v.w;
    }
    float4 rr = make_float4(tanhf(sum.x), tanhf(sum.y), tanhf(sum.z), tanhf(sum.w));
    *(float4*)(out + (size_t)gid * 4) = rr;
}

extern "C" void kernel_launch(void* const* d_in, const int* in_sizes, int n_in,
                              void* d_out, int out_size) {
    const float* x    = (const float*)d_in[0];
    const float* pw   = (const float*)d_in[1];
    const float* kern = (const float*)d_in[2];
    const float* bias = (const float*)d_in[3];
    float* out = (float*)d_out;

    cudaFuncSetAttribute(k_main, cudaFuncAttributeMaxDynamicSharedMemorySize, SM_TOT);

    k_main<<<dim3(NT, NS), 256, SM_TOT>>>(x, pw, kern);
    k_reduce<<<(NP * NU) / 1024, 256>>>(bias, out);
}

// round 7
// speedup vs baseline: 1.5034x; 1.5034x over previous
#include <cuda_runtime.h>
#include <cuda_bf16.h>
#include <cstdint>
#include <cstddef>

#define NP 1024
#define NL 32768
#define NU 64
#define NS 32            /* segments */
#define SEG 1024         /* NL/NS */
#define NT 8             /* row tiles */
#define MT 128           /* rows per main block */
#define KC 32            /* K per chunk */
#define NCH (SEG/KC)     /* 32 */

__device__ float g_partial[(size_t)NS * NP * NU];
__device__ float2 g_agg[(size_t)NS * NP];
__device__ int g_flag[NT * NS];                    // phase-1 publish flags

__device__ __forceinline__ float finf()  { return __int_as_float(0x7f800000); }
__device__ __forceinline__ float fninf() { return __int_as_float(0xff800000); }
__device__ __forceinline__ float fclamp(float v, float a, float b) {
    return fminf(fmaxf(v, a), b);
}
__device__ __forceinline__ uint32_t bfpack(float e0, float e1) {
    uint32_t r;
    asm("cvt.rn.bf16x2.f32 %0, %1, %2;" : "=r"(r) : "f"(e1), "f"(e0));
    return r;
}
__device__ __forceinline__ uint32_t s2u(const void* p) {
    uint32_t a;
    asm("{ .reg .u64 t; cvta.to.shared.u64 t, %1; cvt.u32.u64 %0, t; }"
        : "=r"(a) : "l"(p));
    return a;
}
__device__ __forceinline__ void ldsm4(uint32_t* r, uint32_t a) {
    asm volatile("ldmatrix.sync.aligned.m8n8.x4.shared.b16 {%0,%1,%2,%3}, [%4];"
        : "=r"(r[0]), "=r"(r[1]), "=r"(r[2]), "=r"(r[3]) : "r"(a));
}
__device__ __forceinline__ void ldsm4t(uint32_t* r, uint32_t a) {
    asm volatile("ldmatrix.sync.aligned.m8n8.x4.trans.shared.b16 {%0,%1,%2,%3}, [%4];"
        : "=r"(r[0]), "=r"(r[1]), "=r"(r[2]), "=r"(r[3]) : "r"(a));
}
__device__ __forceinline__ void mma_bf16(float* d, const uint32_t* a,
                                         uint32_t b0, uint32_t b1) {
    asm volatile(
        "mma.sync.aligned.m16n8k16.row.col.f32.bf16.bf16.f32 "
        "{%0,%1,%2,%3}, {%4,%5,%6,%7}, {%8,%9}, {%0,%1,%2,%3};"
        : "+f"(d[0]), "+f"(d[1]), "+f"(d[2]), "+f"(d[3])
        : "r"(a[0]), "r"(a[1]), "r"(a[2]), "r"(a[3]), "r"(b0), "r"(b1));
}
#define BARS(id, cnt) asm volatile("bar.sync %0, %1;"   :: "r"(id), "r"(cnt) : "memory")
#define BARA(id, cnt) asm volatile("bar.arrive %0, %1;" :: "r"(id), "r"(cnt) : "memory")

/* smem layout (bytes) */
#define XS_STR 36                              /* x stage stride, floats (144B) */
#define Y_SLOT(sl) (18432 + (sl) * 20480)      /* hi base; rows stride 80B      */
#define YLO 10240                              /* lo offset within Y slot       */
#define B_SLOT(sl) (59392 + (sl) * 9216)       /* hi base; rows stride 144B     */
#define BLO 4608
#define EX_OFF 77824                           /* phase-1 half exchange (1KB)   */
#define SM_TOT 78848
#define XS2_STR 132                            /* phase-1 stage stride, floats  */

__global__ __launch_bounds__(256, 2) void k_main(const float* __restrict__ x,
                                                 const float* __restrict__ pw,
                                                 const float* __restrict__ kern) {
    extern __shared__ char smem[];
    float* xs = (float*)smem;
    uint32_t sb = s2u(smem);

    int tile = blockIdx.x;        // 0..7
    int s    = blockIdx.y;        // 0..31
    int t    = threadIdx.x;
    int w    = t >> 5, lane = t & 31;
    int r0   = tile * MT;
    const size_t xoff = (size_t)s * SEG;

    // ---------- phase 1: per-row aggregate, two half-threads per row ----------
    int r = t & 127, half = t >> 7;
    int row = r0 + r;
    float pwv = pw[row];
    {
        float A = fninf(), B = finf();
        for (int i = 0; i < 8; ++i) {
            __syncthreads();
            #pragma unroll
            for (int q = 0; q < 16; ++q) {
                int g = q * 256 + t;
                int rr = g >> 5, cc = g & 31;
                size_t gcol = (cc < 16) ? ((size_t)i * 64 + cc * 4)
                                        : (512 + (size_t)i * 64 + (cc - 16) * 4);
                int scol = (cc < 16) ? cc * 4 : 64 + (cc - 16) * 4;
                float4 v = *(const float4*)(x + (size_t)(r0 + rr) * NL + xoff + gcol);
                *(float4*)(xs + rr * XS2_STR + scol) = v;
            }
            __syncthreads();

            const float4* xv = (const float4*)(xs + r * XS2_STR + half * 64);
            int jbase = s * SEG + half * 512 + i * 64;
            int qs = 0;
            if (jbase == 0) {
                float4 v = xv[0];
                A = v.x; B = v.x;            // j==0: clamp (p0,p0)
                float vv[3] = {v.y, v.z, v.w};
                #pragma unroll
                for (int e = 0; e < 3; ++e) {
                    float a = vv[e] * pwv, b = a + 1.0f;
                    A = fclamp(A, a, b);
                    B = fclamp(B, a, b);
                }
                qs = 1;
            }
            for (int q = qs; q < 16; ++q) {
                float4 v = xv[q];
                float vv[4] = {v.x, v.y, v.z, v.w};
                #pragma unroll
                for (int e = 0; e < 4; ++e) {
                    float a = vv[e] * pwv, b = a + 1.0f;
                    A = fclamp(A, a, b);
                    B = fclamp(B, a, b);
                }
            }
        }
        float2* ex = (float2*)(smem + EX_OFF);
        if (half) ex[r] = make_float2(A, B);
        __syncthreads();
        if (!half) {
            float2 ab = ex[r];
            g_agg[(size_t)s * NP + row] =
                make_float2(fclamp(A, ab.x, ab.y), fclamp(B, ab.x, ab.y));
        }
        __threadfence();
        __syncthreads();
        if (t == 0) atomicExch(&g_flag[tile * NS + s], 1);
    }

    // ---------- lookback ----------
    float y = 0.0f;
    if (s > 0) {
        if (t < s)
            while (atomicAdd(&g_flag[tile * NS + t], 0) == 0) { }
        __syncthreads();
        if (t < 128) {
            for (int s2 = 0; s2 < s; ++s2) {
                float2 ab = __ldcg(&g_agg[(size_t)s2 * NP + row]);
                y = fclamp(y, ab.x, ab.y);
            }
        }
    }
    __syncthreads();

    // ---------- pipeline: producers (warps 0-3) / consumers (warps 4-7) ----
    if (t < 128) {
        int p = t;
        for (int c = 0; c < NCH; ++c) {
            int sl = c & 1;
            if (c >= 2) BARS(3 + sl, 256);     // consumers done with slot
            BARS(5, 128);                      // producers done reading xs
            // stage x chunk (coalesced)
            #pragma unroll
            for (int q = 0; q < 8; ++q) {
                int g = q * 128 + p;
                int rr = g >> 3, cc = g & 7;
                float4 v = *(const float4*)(x + (size_t)(r0 + rr) * NL
                                              + xoff + c * KC + cc * 4);
                *(float4*)(xs + rr * XS_STR + cc * 4) = v;
            }
            // convert B chunk from kern (L2) -> bf16 hi/lo, [k][n] layout
            #pragma unroll
            for (int i = 0; i < 4; ++i) {
                int g = i * 512 + p * 4;       // f32 index within 32x64 chunk
                int kr = g >> 6, nc = g & 63;
                float4 v = *(const float4*)(kern
                    + (size_t)(s * SEG + c * KC + kr) * NU + nc);
                uint32_t hp0 = bfpack(v.x, v.y), hp1 = bfpack(v.z, v.w);
                float a0 = __uint_as_float(hp0 << 16);
                float b0 = __uint_as_float(hp0 & 0xffff0000u);
                float a1 = __uint_as_float(hp1 << 16);
                float b1 = __uint_as_float(hp1 & 0xffff0000u);
                uint32_t lp0 = bfpack(v.x - a0, v.y - b0);
                uint32_t lp1 = bfpack(v.z - a1, v.w - b1);
                char* bp = smem + B_SLOT(sl) + kr * 144 + nc * 2;
                *(uint2*)bp         = make_uint2(hp0, hp1);
                *(uint2*)(bp + BLO) = make_uint2(lp0, lp1);
            }
            BARS(5, 128);                      // xs + B ready for this group
            // scan own row; emit bf16 hi/lo Y tiles
            const float4* xv = (const float4*)(xs + p * XS_STR);
            int j0 = s * SEG + c * KC;
            char* yh = smem + Y_SLOT(sl) + p * 80;
            #pragma unroll
            for (int q = 0; q < 4; ++q) {
                float4 v0 = xv[2 * q], v1 = xv[2 * q + 1];
                float vv[8] = {v0.x, v0.y, v0.z, v0.w, v1.x, v1.y, v1.z, v1.w};
                float ya[8];
                int es = 0;
                if (j0 == 0 && q == 0) { y = vv[0]; ya[0] = y; es = 1; }
                #pragma unroll
                for (int e = 0; e < 8; ++e) {
                    if (e < es) continue;
                    float a = vv[e] * pwv, b = a + 1.0f;
                    y = fclamp(y, a, b);
                    ya[e] = y;
                }
                uint32_t h[4], l[4];
                #pragma unroll
                for (int pp = 0; pp < 4; ++pp) {
                    float e0 = ya[2 * pp], e1 = ya[2 * pp + 1];
                    uint32_t hp = bfpack(e0, e1);
                    float h0 = __uint_as_float(hp << 16);
                    float h1 = __uint_as_float(hp & 0xffff0000u);
                    h[pp] = hp;
                    l[pp] = bfpack(e0 - h0, e1 - h1);
                }
                *(uint4*)(yh + q * 16)       = make_uint4(h[0], h[1], h[2], h[3]);
                *(uint4*)(yh + YLO + q * 16) = make_uint4(l[0], l[1], l[2], l[3]);
            }
            BARA(1 + sl, 256);                 // slot full
        }
        BARS(3, 256);                          // drain final empties
        BARS(4, 256);
    } else {
        int cw = w - 4;
        float acc[2][8][4];
        #pragma unroll
        for (int i = 0; i < 2; ++i)
            #pragma unroll
            for (int j = 0; j < 8; ++j)
                #pragma unroll
                for (int q = 0; q < 4; ++q) acc[i][j][q] = 0.0f;

        for (int c = 0; c < NCH; ++c) {
            int sl = c & 1;
            BARS(1 + sl, 256);                 // wait slot full
            #pragma unroll
            for (int kk = 0; kk < 2; ++kk) {
                uint32_t ah[2][4], al[2][4];
                #pragma unroll
                for (int mt = 0; mt < 2; ++mt) {
                    uint32_t ra = sb + Y_SLOT(sl)
                        + (uint32_t)(cw * 32 + mt * 16 + (lane & 15)) * 80
                        + (uint32_t)(kk * 16 + (lane >> 4) * 8) * 2;
                    ldsm4(ah[mt], ra);
                    ldsm4(al[mt], ra + YLO);
                }
                #pragma unroll
                for (int np = 0; np < 4; ++np) {
                    uint32_t rb = sb + B_SLOT(sl)
                        + (uint32_t)(kk * 16 + (lane & 15)) * 144
                        + (uint32_t)(np * 16 + (lane >> 4) * 8) * 2;
                    uint32_t bh[4], bl[4];
                    ldsm4t(bh, rb);
                    ldsm4t(bl, rb + BLO);
                    #pragma unroll
                    for (int mt = 0; mt < 2; ++mt) {
                        mma_bf16(acc[mt][2 * np],     ah[mt], bh[0], bh[1]);
                        mma_bf16(acc[mt][2 * np],     ah[mt], bl[0], bl[1]);
                        mma_bf16(acc[mt][2 * np],     al[mt], bh[0], bh[1]);
                        mma_bf16(acc[mt][2 * np + 1], ah[mt], bh[2], bh[3]);
                        mma_bf16(acc[mt][2 * np + 1], ah[mt], bl[2], bl[3]);
                        mma_bf16(acc[mt][2 * np + 1], al[mt], bh[2], bh[3]);
                    }
                }
            }
            BARA(3 + sl, 256);                 // slot empty
        }
        // epilogue: deterministic per-segment partials [s][p][u]
        #pragma unroll
        for (int mt = 0; mt < 2; ++mt) {
            int p = r0 + cw * 32 + mt * 16 + (lane >> 2);
            #pragma unroll
            for (int nt = 0; nt < 8; ++nt) {
                int u = nt * 8 + (lane & 3) * 2;
                *(float2*)&g_partial[((size_t)s * NP + p) * NU + u] =
                    make_float2(acc[mt][nt][0], acc[mt][nt][1]);
                *(float2*)&g_partial[((size_t)s * NP + p + 8) * NU + u] =
                    make_float2(acc[mt][nt][2], acc[mt][nt][3]);
            }
        }
    }
}

// ---------------------------------------------------------------------------
// Reduction + bias + tanh; resets flags for the next graph replay.
// ---------------------------------------------------------------------------
__global__ __launch_bounds__(256) void k_reduce(const float* __restrict__ bias,
                                                float* __restrict__ out) {
    int idx = blockIdx.x * 256 + threadIdx.x;       // float2 units, 0..32767
    if (blockIdx.x == 0) g_flag[threadIdx.x] = 0;
    float2 sum = *(const float2*)(bias + ((idx * 2) & (NU - 1)));
    #pragma unroll 8
    for (int s2 = 0; s2 < NS; ++s2) {
        float2 v = *(const float2*)(g_partial + (size_t)s2 * (NP * NU) + (size_t)idx * 2);
        sum.x += v.x; sum.y += v.y;
    }
    *(float2*)(out + (size_t)idx * 2) = make_float2(tanhf(sum.x), tanhf(sum.y));
}

extern "C" void kernel_launch(void* const* d_in, const int* in_sizes, int n_in,
                              void* d_out, int out_size) {
    const float* x    = (const float*)d_in[0];
    const float* pw   = (const float*)d_in[1];
    const float* kern = (const float*)d_in[2];
    const float* bias = (const float*)d_in[3];
    float* out = (float*)d_out;

    cudaFuncSetAttribute(k_main, cudaFuncAttributeMaxDynamicSharedMemorySize, SM_TOT);

    k_main<<<dim3(NT, NS), 256, SM_TOT>>>(x, pw, kern);
    k_reduce<<<(NP * NU) / 512, 256>>>(bias, out);
}

// round 8
// speedup vs baseline: 1.5756x; 1.0480x over previous
#include <cuda_runtime.h>
#include <cuda_bf16.h>
#include <cstdint>
#include <cstddef>

#define NP 1024
#define NL 32768
#define NU 64
#define NS 32            /* segments */
#define SEG 1024         /* NL/NS */
#define NT 8             /* row tiles */
#define MT 128           /* rows per main block */
#define KC 32            /* K per chunk */
#define NCH (SEG/KC)     /* 32 */

__device__ float g_partial[(size_t)NS * NP * NU];
__device__ float2 g_agg[(size_t)NS * NP];
__device__ int g_flag[NT * NS];                    // phase-1 publish flags

__device__ __forceinline__ float finf()  { return __int_as_float(0x7f800000); }
__device__ __forceinline__ float fninf() { return __int_as_float(0xff800000); }
__device__ __forceinline__ float fclamp(float v, float a, float b) {
    return fminf(fmaxf(v, a), b);
}
__device__ __forceinline__ uint32_t bfpack(float e0, float e1) {
    uint32_t r;
    asm("cvt.rn.bf16x2.f32 %0, %1, %2;" : "=r"(r) : "f"(e1), "f"(e0));
    return r;
}
__device__ __forceinline__ uint32_t s2u(const void* p) {
    uint32_t a;
    asm("{ .reg .u64 t; cvta.to.shared.u64 t, %1; cvt.u32.u64 %0, t; }"
        : "=r"(a) : "l"(p));
    return a;
}
__device__ __forceinline__ void ldsm4(uint32_t* r, uint32_t a) {
    asm volatile("ldmatrix.sync.aligned.m8n8.x4.shared.b16 {%0,%1,%2,%3}, [%4];"
        : "=r"(r[0]), "=r"(r[1]), "=r"(r[2]), "=r"(r[3]) : "r"(a));
}
__device__ __forceinline__ void ldsm4t(uint32_t* r, uint32_t a) {
    asm volatile("ldmatrix.sync.aligned.m8n8.x4.trans.shared.b16 {%0,%1,%2,%3}, [%4];"
        : "=r"(r[0]), "=r"(r[1]), "=r"(r[2]), "=r"(r[3]) : "r"(a));
}
__device__ __forceinline__ void mma_bf16(float* d, const uint32_t* a,
                                         uint32_t b0, uint32_t b1) {
    asm volatile(
        "mma.sync.aligned.m16n8k16.row.col.f32.bf16.bf16.f32 "
        "{%0,%1,%2,%3}, {%4,%5,%6,%7}, {%8,%9}, {%0,%1,%2,%3};"
        : "+f"(d[0]), "+f"(d[1]), "+f"(d[2]), "+f"(d[3])
        : "r"(a[0]), "r"(a[1]), "r"(a[2]), "r"(a[3]), "r"(b0), "r"(b1));
}
#define BARS(id, cnt) asm volatile("bar.sync %0, %1;"   :: "r"(id), "r"(cnt) : "memory")
#define BARA(id, cnt) asm volatile("bar.arrive %0, %1;" :: "r"(id), "r"(cnt) : "memory")

/* smem layout (bytes) */
#define XS_STR 36                              /* x stage stride, floats (144B) */
#define Y_SLOT(sl) (18432 + (sl) * 20480)      /* hi base; rows stride 80B      */
#define YLO 10240
#define B_SLOT(sl) (59392 + (sl) * 9216)       /* hi base; rows stride 144B     */
#define BLO 4608
#define EX_OFF 77824                           /* phase-1 half exchange (1KB)   */
#define SM_TOT 78848
#define XS2_STR 132                            /* phase-1 stage stride, floats  */

__global__ __launch_bounds__(256, 2) void k_main(const float* __restrict__ x,
                                                 const float* __restrict__ pw,
                                                 const float* __restrict__ kern) {
    extern __shared__ char smem[];
    float* xs = (float*)smem;
    uint32_t sb = s2u(smem);

    int tile = blockIdx.x;        // 0..7
    int s    = blockIdx.y;        // 0..31
    int t    = threadIdx.x;
    int w    = t >> 5, lane = t & 31;
    int r0   = tile * MT;
    const size_t xoff = (size_t)s * SEG;

    // ---------- phase 1: per-row aggregate, two half-threads per row --------
    // Reverse piece order (per-piece aggregates are order-independent; only
    // the final fold is ordered) so phase 2's earliest chunks are L2-hot.
    int r = t & 127, half = t >> 7;
    int row = r0 + r;
    float pwv = pw[row];
    {
        float pA[8], pB[8];
        float4 rbuf[16];
        // preload piece i=7
        #pragma unroll
        for (int q = 0; q < 16; ++q) {
            int g = q * 256 + t;
            int rr = g >> 5, cc = g & 31;
            size_t gcol = (cc < 16) ? (7 * 64 + (size_t)cc * 4)
                                    : (512 + 7 * 64 + (size_t)(cc - 16) * 4);
            rbuf[q] = *(const float4*)(x + (size_t)(r0 + rr) * NL + xoff + gcol);
        }
        for (int it = 0; it < 8; ++it) {
            int i = 7 - it;
            __syncthreads();
            #pragma unroll
            for (int q = 0; q < 16; ++q) {
                int g = q * 256 + t;
                int rr = g >> 5, cc = g & 31;
                int scol = (cc < 16) ? cc * 4 : 64 + (cc - 16) * 4;
                *(float4*)(xs + rr * XS2_STR + scol) = rbuf[q];
            }
            if (it < 7) {
                int ni = i - 1;
                #pragma unroll
                for (int q = 0; q < 16; ++q) {
                    int g = q * 256 + t;
                    int rr = g >> 5, cc = g & 31;
                    size_t gcol = (cc < 16) ? ((size_t)ni * 64 + (size_t)cc * 4)
                                            : (512 + (size_t)ni * 64 + (size_t)(cc - 16) * 4);
                    rbuf[q] = *(const float4*)(x + (size_t)(r0 + rr) * NL + xoff + gcol);
                }
            }
            __syncthreads();

            const float4* xv = (const float4*)(xs + r * XS2_STR + half * 64);
            int jbase = s * SEG + half * 512 + i * 64;
            float A = fninf(), B = finf();
            int qs = 0;
            if (jbase == 0) {
                float4 v = xv[0];
                A = v.x; B = v.x;            // j==0: clamp (p0,p0)
                float vv[3] = {v.y, v.z, v.w};
                #pragma unroll
                for (int e = 0; e < 3; ++e) {
                    float a = vv[e] * pwv, b = a + 1.0f;
                    A = fclamp(A, a, b);
                    B = fclamp(B, a, b);
                }
                qs = 1;
            }
            for (int q = qs; q < 16; ++q) {
                float4 v = xv[q];
                float vv[4] = {v.x, v.y, v.z, v.w};
                #pragma unroll
                for (int e = 0; e < 4; ++e) {
                    float a = vv[e] * pwv, b = a + 1.0f;
                    A = fclamp(A, a, b);
                    B = fclamp(B, a, b);
                }
            }
            pA[i] = A; pB[i] = B;
        }
        // ordered fold i=0..7
        float A = pA[0], B = pB[0];
        #pragma unroll
        for (int i = 1; i < 8; ++i) {
            A = fclamp(A, pA[i], pB[i]);
            B = fclamp(B, pA[i], pB[i]);
        }
        float2* ex = (float2*)(smem + EX_OFF);
        if (half) ex[r] = make_float2(A, B);
        __syncthreads();
        if (!half) {
            float2 ab = ex[r];
            g_agg[(size_t)s * NP + row] =
                make_float2(fclamp(A, ab.x, ab.y), fclamp(B, ab.x, ab.y));
        }
        __threadfence();
        __syncthreads();
        if (t == 0) atomicExch(&g_flag[tile * NS + s], 1);
    }

    // ---------- lookback ----------
    float y = 0.0f;
    if (s > 0) {
        if (t < s)
            while (atomicAdd(&g_flag[tile * NS + t], 0) == 0) { }
        __syncthreads();
        if (t < 128) {
            for (int s2 = 0; s2 < s; ++s2) {
                float2 ab = __ldcg(&g_agg[(size_t)s2 * NP + row]);
                y = fclamp(y, ab.x, ab.y);
            }
        }
    }
    __syncthreads();

    // ---------- pipeline: producers (warps 0-3) / consumers (warps 4-7) ----
    if (t < 128) {
        int p = t;
        float4 xbuf[8], bbuf[4];
        // preload chunk 0
        #pragma unroll
        for (int q = 0; q < 8; ++q) {
            int g = q * 128 + p;
            int rr = g >> 3, cc = g & 7;
            xbuf[q] = *(const float4*)(x + (size_t)(r0 + rr) * NL + xoff + cc * 4);
        }
        #pragma unroll
        for (int i = 0; i < 4; ++i) {
            int g = i * 512 + p * 4;
            int kr = g >> 6, nc = g & 63;
            bbuf[i] = *(const float4*)(kern + (size_t)(s * SEG + kr) * NU + nc);
        }

        for (int c = 0; c < NCH; ++c) {
            int sl = c & 1;
            if (c >= 2) BARS(3 + sl, 256);     // consumers done with slot
            BARS(5, 128);                      // producer scans done reading xs
            // commit prefetched x chunk
            #pragma unroll
            for (int q = 0; q < 8; ++q) {
                int g = q * 128 + p;
                int rr = g >> 3, cc = g & 7;
                *(float4*)(xs + rr * XS_STR + cc * 4) = xbuf[q];
            }
            // convert prefetched B chunk -> bf16 hi/lo, [k][n]
            #pragma unroll
            for (int i = 0; i < 4; ++i) {
                int g = i * 512 + p * 4;
                int kr = g >> 6, nc = g & 63;
                float4 v = bbuf[i];
                uint32_t hp0 = bfpack(v.x, v.y), hp1 = bfpack(v.z, v.w);
                float a0 = __uint_as_float(hp0 << 16);
                float b0 = __uint_as_float(hp0 & 0xffff0000u);
                float a1 = __uint_as_float(hp1 << 16);
                float b1 = __uint_as_float(hp1 & 0xffff0000u);
                uint32_t lp0 = bfpack(v.x - a0, v.y - b0);
                uint32_t lp1 = bfpack(v.z - a1, v.w - b1);
                char* bp = smem + B_SLOT(sl) + kr * 144 + nc * 2;
                *(uint2*)bp         = make_uint2(hp0, hp1);
                *(uint2*)(bp + BLO) = make_uint2(lp0, lp1);
            }
            // prefetch next chunk (latency hidden behind scan + mma wait)
            if (c < NCH - 1) {
                #pragma unroll
                for (int q = 0; q < 8; ++q) {
                    int g = q * 128 + p;
                    int rr = g >> 3, cc = g & 7;
                    xbuf[q] = *(const float4*)(x + (size_t)(r0 + rr) * NL
                                                 + xoff + (c + 1) * KC + cc * 4);
                }
                #pragma unroll
                for (int i = 0; i < 4; ++i) {
                    int g = i * 512 + p * 4;
                    int kr = g >> 6, nc = g & 63;
                    bbuf[i] = *(const float4*)(kern
                        + (size_t)(s * SEG + (c + 1) * KC + kr) * NU + nc);
                }
            }
            BARS(5, 128);                      // xs + B ready
            // scan own row; emit bf16 hi/lo Y tiles
            const float4* xv = (const float4*)(xs + p * XS_STR);
            int j0 = s * SEG + c * KC;
            char* yh = smem + Y_SLOT(sl) + p * 80;
            #pragma unroll
            for (int q = 0; q < 4; ++q) {
                float4 v0 = xv[2 * q], v1 = xv[2 * q + 1];
                float vv[8] = {v0.x, v0.y, v0.z, v0.w, v1.x, v1.y, v1.z, v1.w};
                float ya[8];
                int es = 0;
                if (j0 == 0 && q == 0) { y = vv[0]; ya[0] = y; es = 1; }
                #pragma unroll
                for (int e = 0; e < 8; ++e) {
                    if (e < es) continue;
                    float a = vv[e] * pwv, b = a + 1.0f;
                    y = fclamp(y, a, b);
                    ya[e] = y;
                }
                uint32_t h[4], l[4];
                #pragma unroll
                for (int pp = 0; pp < 4; ++pp) {
                    float e0 = ya[2 * pp], e1 = ya[2 * pp + 1];
                    uint32_t hp = bfpack(e0, e1);
                    float h0 = __uint_as_float(hp << 16);
                    float h1 = __uint_as_float(hp & 0xffff0000u);
                    h[pp] = hp;
                    l[pp] = bfpack(e0 - h0, e1 - h1);
                }
                *(uint4*)(yh + q * 16)       = make_uint4(h[0], h[1], h[2], h[3]);
                *(uint4*)(yh + YLO + q * 16) = make_uint4(l[0], l[1], l[2], l[3]);
            }
            BARA(1 + sl, 256);                 // slot full
        }
        BARS(3, 256);                          // drain final empties
        BARS(4, 256);
    } else {
        int cw = w - 4;
        float acc[2][8][4];
        #pragma unroll
        for (int i = 0; i < 2; ++i)
            #pragma unroll
            for (int j = 0; j < 8; ++j)
                #pragma unroll
                for (int q = 0; q < 4; ++q) acc[i][j][q] = 0.0f;

        for (int c = 0; c < NCH; ++c) {
            int sl = c & 1;
            BARS(1 + sl, 256);                 // wait slot full
            #pragma unroll
            for (int kk = 0; kk < 2; ++kk) {
                uint32_t ah[2][4], al[2][4];
                #pragma unroll
                for (int mt = 0; mt < 2; ++mt) {
                    uint32_t ra = sb + Y_SLOT(sl)
                        + (uint32_t)(cw * 32 + mt * 16 + (lane & 15)) * 80
                        + (uint32_t)(kk * 16 + (lane >> 4) * 8) * 2;
                    ldsm4(ah[mt], ra);
                    ldsm4(al[mt], ra + YLO);
                }
                #pragma unroll
                for (int np = 0; np < 4; ++np) {
                    uint32_t rb = sb + B_SLOT(sl)
                        + (uint32_t)(kk * 16 + (lane & 15)) * 144
                        + (uint32_t)(np * 16 + (lane >> 4) * 8) * 2;
                    uint32_t bh[4], bl[4];
                    ldsm4t(bh, rb);
                    ldsm4t(bl, rb + BLO);
                    #pragma unroll
                    for (int mt = 0; mt < 2; ++mt) {
                        mma_bf16(acc[mt][2 * np],     ah[mt], bh[0], bh[1]);
                        mma_bf16(acc[mt][2 * np],     ah[mt], bl[0], bl[1]);
                        mma_bf16(acc[mt][2 * np],     al[mt], bh[0], bh[1]);
                        mma_bf16(acc[mt][2 * np + 1], ah[mt], bh[2], bh[3]);
                        mma_bf16(acc[mt][2 * np + 1], ah[mt], bl[2], bl[3]);
                        mma_bf16(acc[mt][2 * np + 1], al[mt], bh[2], bh[3]);
                    }
                }
            }
            BARA(3 + sl, 256);                 // slot empty
        }
        // epilogue: deterministic per-segment partials [s][p][u]
        #pragma unroll
        for (int mt = 0; mt < 2; ++mt) {
            int p = r0 + cw * 32 + mt * 16 + (lane >> 2);
            #pragma unroll
            for (int nt = 0; nt < 8; ++nt) {
                int u = nt * 8 + (lane & 3) * 2;
                *(float2*)&g_partial[((size_t)s * NP + p) * NU + u] =
                    make_float2(acc[mt][nt][0], acc[mt][nt][1]);
                *(float2*)&g_partial[((size_t)s * NP + p + 8) * NU + u] =
                    make_float2(acc[mt][nt][2], acc[mt][nt][3]);
            }
        }
    }
}

// ---------------------------------------------------------------------------
// Reduction + bias + tanh; resets flags for the next graph replay.
// ---------------------------------------------------------------------------
__global__ __launch_bounds__(256) void k_reduce(const float* __restrict__ bias,
                                                float* __restrict__ out) {
    int idx = blockIdx.x * 256 + threadIdx.x;       // 0..65535
    if (blockIdx.x == 0) g_flag[threadIdx.x] = 0;
    float sum = bias[idx & (NU - 1)];
    #pragma unroll 8
    for (int s2 = 0; s2 < NS; ++s2)
        sum += g_partial[(size_t)s2 * (NP * NU) + idx];
    out[idx] = tanhf(sum);
}

extern "C" void kernel_launch(void* const* d_in, const int* in_sizes, int n_in,
                              void* d_out, int out_size) {
    const float* x    = (const float*)d_in[0];
    const float* pw   = (const float*)d_in[1];
    const float* kern = (const float*)d_in[2];
    const float* bias = (const float*)d_in[3];
    float* out = (float*)d_out;

    cudaFuncSetAttribute(k_main, cudaFuncAttributeMaxDynamicSharedMemorySize, SM_TOT);

    k_main<<<dim3(NT, NS), 256, SM_TOT>>>(x, pw, kern);
    k_reduce<<<(NP * NU) / 256, 256>>>(bias, out);
}